// round 2
// baseline (speedup 1.0000x reference)
#include <cuda_runtime.h>
#include <math.h>

// Problem constants (fixed by the reference setup)
#define BB   256      // batch
#define CC   3        // channels
#define HWD  16384    // H*W = 128*128
#define KCH  4        // MH chain steps (BURNIN*NUM_SAMPLES)
#define NST  5        // states evaluated: s0 + 4 candidates
#define NCL  10       // classes

// Tiling
#define BG    8               // batches per block (8 warps)
#define PC    8               // pixel chunks
#define CHUNK (HWD / PC)      // 2048 pixels per chunk

// Scratch (static device arrays: allocation-free)
__device__ float g_Wt[NCL * CC * HWD];          // W transposed: [n][c][p]
__device__ float g_partial[PC * NST * BB * NCL];

// ---------------------------------------------------------------------------
// K0: transpose W [CC*HWD, NCL] -> Wt [n][c][p] for coalesced main-loop loads
// ---------------------------------------------------------------------------
__global__ void prep_kernel(const float* __restrict__ W)
{
    int r = blockIdx.x * blockDim.x + threadIdx.x;   // r in [0, CC*HWD)
    if (r < CC * HWD) {
        int c = r / HWD;
        int p = r - c * HWD;
#pragma unroll
        for (int n = 0; n < NCL; n++)
            g_Wt[(n * CC + c) * HWD + p] = W[r * NCL + n];
    }
}

// ---------------------------------------------------------------------------
// K1: fused mask generation + 5-state masked classifier partial sums.
// Grid: (PC pixel-chunks, BB/BG batch-groups). Block: BG warps.
// Warp w handles batch blockIdx.y*BG + w over pixel chunk blockIdx.x.
// Each lane processes 4 consecutive pixels per iteration (float4 loads).
// ---------------------------------------------------------------------------
__global__ __launch_bounds__(BG * 32)
void main_kernel(const float* __restrict__ zl,
                 const float* __restrict__ x,
                 const float* __restrict__ bern)
{
    const int warp = threadIdx.x >> 5;
    const int lane = threadIdx.x & 31;
    const int b     = blockIdx.y * BG + warp;
    const int pbase = blockIdx.x * CHUNK;

    const float4* z4  = reinterpret_cast<const float4*>(zl + b * HWD + pbase);
    const float4* x40 = reinterpret_cast<const float4*>(x + (b * CC + 0) * HWD + pbase);
    const float4* x41 = reinterpret_cast<const float4*>(x + (b * CC + 1) * HWD + pbase);
    const float4* x42 = reinterpret_cast<const float4*>(x + (b * CC + 2) * HWD + pbase);
    const float4* bn0 = reinterpret_cast<const float4*>(bern + (0 * BB + b) * HWD + pbase);
    const float4* bn1 = reinterpret_cast<const float4*>(bern + (1 * BB + b) * HWD + pbase);
    const float4* bn2 = reinterpret_cast<const float4*>(bern + (2 * BB + b) * HWD + pbase);
    const float4* bn3 = reinterpret_cast<const float4*>(bern + (3 * BB + b) * HWD + pbase);
    const float4* wt4 = reinterpret_cast<const float4*>(g_Wt);
    const int wbase = pbase >> 2;   // float4 offset of this chunk within a (n,c) plane

    float acc[NST][NCL];
#pragma unroll
    for (int kk = 0; kk < NST; kk++)
#pragma unroll
        for (int n = 0; n < NCL; n++) acc[kk][n] = 0.0f;

    const int NIT = CHUNK / 4;   // 512 float4 groups per chunk
    for (int i = lane; i < NIT; i += 32) {
        float4 z = z4[i];
        float zv[4] = { z.x, z.y, z.z, z.w };

        float4 xa = x40[i], xb = x41[i], xc = x42[i];
        float xv0[4] = { xa.x, xa.y, xa.z, xa.w };
        float xv1[4] = { xb.x, xb.y, xb.z, xb.w };
        float xv2[4] = { xc.x, xc.y, xc.z, xc.w };

        // per-pixel sigmoid + 5 masks
        float zp[4];
        float m[NST][4];
#pragma unroll
        for (int j = 0; j < 4; j++) {
            zp[j]   = 1.0f / (1.0f + __expf(-zv[j]));
            m[0][j] = (zv[j] >= 0.0f) ? 1.0f : 0.0f;   // sigmoid(zl)>=0.5 <=> zl>=0
        }
        {
            float4 bq = bn0[i]; float bv[4] = { bq.x, bq.y, bq.z, bq.w };
#pragma unroll
            for (int j = 0; j < 4; j++) m[1][j] = (bv[j] < zp[j]) ? 1.0f : 0.0f;
        }
        {
            float4 bq = bn1[i]; float bv[4] = { bq.x, bq.y, bq.z, bq.w };
#pragma unroll
            for (int j = 0; j < 4; j++) m[2][j] = (bv[j] < zp[j]) ? 1.0f : 0.0f;
        }
        {
            float4 bq = bn2[i]; float bv[4] = { bq.x, bq.y, bq.z, bq.w };
#pragma unroll
            for (int j = 0; j < 4; j++) m[3][j] = (bv[j] < zp[j]) ? 1.0f : 0.0f;
        }
        {
            float4 bq = bn3[i]; float bv[4] = { bq.x, bq.y, bq.z, bq.w };
#pragma unroll
            for (int j = 0; j < 4; j++) m[4][j] = (bv[j] < zp[j]) ? 1.0f : 0.0f;
        }

        // per class: channel dot then masked accumulate into 5 states
#pragma unroll
        for (int n = 0; n < NCL; n++) {
            float4 w0 = wt4[(n * CC + 0) * (HWD / 4) + wbase + i];
            float4 w1 = wt4[(n * CC + 1) * (HWD / 4) + wbase + i];
            float4 w2 = wt4[(n * CC + 2) * (HWD / 4) + wbase + i];
            float wv0[4] = { w0.x, w0.y, w0.z, w0.w };
            float wv1[4] = { w1.x, w1.y, w1.z, w1.w };
            float wv2[4] = { w2.x, w2.y, w2.z, w2.w };
#pragma unroll
            for (int j = 0; j < 4; j++) {
                float v = fmaf(xv0[j], wv0[j],
                          fmaf(xv1[j], wv1[j],
                               xv2[j] * wv2[j]));
#pragma unroll
                for (int kk = 0; kk < NST; kk++)
                    acc[kk][n] = fmaf(m[kk][j], v, acc[kk][n]);
            }
        }
    }

    // warp butterfly reduce (each warp = one batch)
#pragma unroll
    for (int kk = 0; kk < NST; kk++)
#pragma unroll
        for (int n = 0; n < NCL; n++) {
            float v = acc[kk][n];
#pragma unroll
            for (int off = 16; off > 0; off >>= 1)
                v += __shfl_xor_sync(0xffffffffu, v, off);
            acc[kk][n] = v;
        }

    if (lane == 0) {
#pragma unroll
        for (int kk = 0; kk < NST; kk++)
#pragma unroll
            for (int n = 0; n < NCL; n++)
                g_partial[((blockIdx.x * NST + kk) * BB + b) * NCL + n] = acc[kk][n];
    }
}

// ---------------------------------------------------------------------------
// K2: sum chunk partials, log-softmax -> pz, MH chain, select, write output.
// One thread per batch.
// ---------------------------------------------------------------------------
__global__ void final_kernel(const int* __restrict__ y,
                             const float* __restrict__ u,
                             const float* __restrict__ bias,
                             float* __restrict__ out)
{
    int b = blockIdx.x * blockDim.x + threadIdx.x;
    if (b >= BB) return;

    float logits[NST][NCL];
#pragma unroll
    for (int kk = 0; kk < NST; kk++)
#pragma unroll
        for (int n = 0; n < NCL; n++) {
            float s = 0.0f;
#pragma unroll
            for (int pc = 0; pc < PC; pc++)
                s += g_partial[((pc * NST + kk) * BB + b) * NCL + n];
            logits[kk][n] = s + bias[n];
        }

    int yb = y[b];
    float pz[NST];
#pragma unroll
    for (int kk = 0; kk < NST; kk++) {
        float mx = logits[kk][0];
#pragma unroll
        for (int n = 1; n < NCL; n++) mx = fmaxf(mx, logits[kk][n]);
        float se = 0.0f;
#pragma unroll
        for (int n = 0; n < NCL; n++) se += expf(logits[kk][n] - mx);
        float lse = mx + logf(se);
        float ly = logits[kk][0];
#pragma unroll
        for (int n = 0; n < NCL; n++) if (n == yb) ly = logits[kk][n];
        pz[kk] = ly - lse;
    }

    // MH chain: accept when log(u) <= pz_cand - lp
    int sel = 0;
    float lp = pz[0];
#pragma unroll
    for (int k = 1; k < NST; k++) {
        float lu = logf(u[(k - 1) * BB + b]);
        if (lu <= pz[k] - lp) { sel = k; lp = pz[k]; }
    }

#pragma unroll
    for (int n = 0; n < NCL; n++) {
        float v = logits[0][n];
#pragma unroll
        for (int kk = 1; kk < NST; kk++) if (kk == sel) v = logits[kk][n];
        out[b * NCL + n] = v;
    }
}

// ---------------------------------------------------------------------------
extern "C" void kernel_launch(void* const* d_in, const int* in_sizes, int n_in,
                              void* d_out, int out_size)
{
    const float* zl   = (const float*)d_in[0];   // [256,1,128,128]
    const float* x    = (const float*)d_in[1];   // [256,3,128,128]
    const int*   y    = (const int*)  d_in[2];   // [256]
    const float* bern = (const float*)d_in[3];   // [4,256,1,128,128]
    const float* u    = (const float*)d_in[4];   // [4,256]
    const float* W    = (const float*)d_in[5];   // [49152,10]
    const float* bias = (const float*)d_in[6];   // [10]
    float* out = (float*)d_out;                  // [256,10]

    prep_kernel<<<(CC * HWD + 255) / 256, 256>>>(W);

    dim3 grid(PC, BB / BG);
    main_kernel<<<grid, BG * 32>>>(zl, x, bern);

    final_kernel<<<1, BB>>>(y, u, bias, out);
}

// round 3
// speedup vs baseline: 1.1921x; 1.1921x over previous
#include <cuda_runtime.h>
#include <math.h>

// Problem constants (fixed by the reference setup)
#define BB   256      // batch
#define CC   3        // channels
#define HWD  16384    // H*W = 128*128
#define NST  5        // states evaluated: s0 + 4 candidates
#define NCL  10       // classes
#define NQ   5        // class pairs (NCL/2)

// Tiling
#define BG     4              // batches per block (4 warps, 128 threads)
#define SLOTS  7              // pixel slots per batch plane (448 blocks ~ 3/SM wave)
#define GROUPS (HWD / 4)      // 4096 float4 groups per plane

typedef unsigned long long u64;

// Scratch (static device arrays: allocation-free)
__device__ ulonglong2 g_Wp[CC * NQ * HWD / 2];     // W packed: [c][q][pixel]{class2q,class2q+1}
__device__ float g_partial[SLOTS * NST * BB * NCL];

// ---------------------------------------------------------------------------
// f32x2 packed-math helpers (sm_100+)
// ---------------------------------------------------------------------------
__device__ __forceinline__ u64 pack2(float lo, float hi) {
    u64 r; asm("mov.b64 %0, {%1, %2};" : "=l"(r) : "f"(lo), "f"(hi)); return r;
}
__device__ __forceinline__ u64 fma2(u64 a, u64 b, u64 c) {
    u64 d; asm("fma.rn.f32x2 %0, %1, %2, %3;" : "=l"(d) : "l"(a), "l"(b), "l"(c)); return d;
}
__device__ __forceinline__ u64 mul2(u64 a, u64 b) {
    u64 d; asm("mul.rn.f32x2 %0, %1, %2;" : "=l"(d) : "l"(a), "l"(b)); return d;
}
__device__ __forceinline__ u64 add2(u64 a, u64 b) {
    u64 d; asm("add.rn.f32x2 %0, %1, %2;" : "=l"(d) : "l"(a), "l"(b)); return d;
}
__device__ __forceinline__ void unpack2(u64 v, float& lo, float& hi) {
    asm("mov.b64 {%0, %1}, %2;" : "=f"(lo), "=f"(hi) : "l"(v));
}
// packed {1.0f,1.0f} or {0,0} from a predicate
__device__ __forceinline__ u64 msel(bool c) {
    return c ? 0x3f8000003f800000ULL : 0ULL;
}

// ---------------------------------------------------------------------------
// K0: repack W [CC*HWD, NCL] -> g_Wp [c][q][p] with class pairs adjacent
// ---------------------------------------------------------------------------
__global__ void prep_kernel(const float* __restrict__ W)
{
    int r = blockIdx.x * blockDim.x + threadIdx.x;   // r in [0, CC*HWD)
    if (r < CC * HWD) {
        int c = r / HWD;
        int p = r - c * HWD;
        float v[NCL];
#pragma unroll
        for (int n = 0; n < NCL; n++) v[n] = W[r * NCL + n];
        float2* wp2 = reinterpret_cast<float2*>(g_Wp);
#pragma unroll
        for (int q = 0; q < NQ; q++) {
            float2 f; f.x = v[2 * q]; f.y = v[2 * q + 1];
            wp2[(c * NQ + q) * HWD + p] = f;
        }
    }
}

// ---------------------------------------------------------------------------
// K1: fused mask generation + 5-state masked classifier partial sums.
// Grid: (SLOTS, BB/BG). Block: BG warps; warp w = batch blockIdx.y*BG + w.
// Each warp accumulates its whole pixel slot (packed class-pair f32x2 accs),
// reduces once at the end.
// ---------------------------------------------------------------------------
__global__ __launch_bounds__(BG * 32, 3)
void main_kernel(const float* __restrict__ zl,
                 const float* __restrict__ x,
                 const float* __restrict__ bern)
{
    const int warp = threadIdx.x >> 5;
    const int lane = threadIdx.x & 31;
    const int b    = blockIdx.y * BG + warp;
    const int s    = blockIdx.x;

    const int lo = (s * GROUPS) / SLOTS;
    const int hi = ((s + 1) * GROUPS) / SLOTS;

    const float4* z4  = reinterpret_cast<const float4*>(zl) + b * GROUPS;
    const float4* x40 = reinterpret_cast<const float4*>(x) + (b * CC + 0) * GROUPS;
    const float4* x41 = reinterpret_cast<const float4*>(x) + (b * CC + 1) * GROUPS;
    const float4* x42 = reinterpret_cast<const float4*>(x) + (b * CC + 2) * GROUPS;
    const float4* bn0 = reinterpret_cast<const float4*>(bern) + (0 * BB + b) * GROUPS;
    const float4* bn1 = reinterpret_cast<const float4*>(bern) + (1 * BB + b) * GROUPS;
    const float4* bn2 = reinterpret_cast<const float4*>(bern) + (2 * BB + b) * GROUPS;
    const float4* bn3 = reinterpret_cast<const float4*>(bern) + (3 * BB + b) * GROUPS;

    u64 acc[NST][NQ];
#pragma unroll
    for (int kk = 0; kk < NST; kk++)
#pragma unroll
        for (int q = 0; q < NQ; q++) acc[kk][q] = 0ULL;

    for (int g = lo + lane; g < hi; g += 32) {
        float4 zq = z4[g];
        float4 xq0 = x40[g], xq1 = x41[g], xq2 = x42[g];
        float4 c0 = bn0[g], c1 = bn1[g], c2 = bn2[g], c3 = bn3[g];

        float za[4]  = { zq.x, zq.y, zq.z, zq.w };
        float xa0[4] = { xq0.x, xq0.y, xq0.z, xq0.w };
        float xa1[4] = { xq1.x, xq1.y, xq1.z, xq1.w };
        float xa2[4] = { xq2.x, xq2.y, xq2.z, xq2.w };
        float ba0[4] = { c0.x, c0.y, c0.z, c0.w };
        float ba1[4] = { c1.x, c1.y, c1.z, c1.w };
        float ba2[4] = { c2.x, c2.y, c2.z, c2.w };
        float ba3[4] = { c3.x, c3.y, c3.z, c3.w };

        float zp[4];
#pragma unroll
        for (int j = 0; j < 4; j++)
            zp[j] = 1.0f / (1.0f + __expf(-za[j]));

        const ulonglong2* wpg = g_Wp + 2 * g;

#pragma unroll
        for (int jp = 0; jp < 2; jp++) {
            const int p0 = 2 * jp, p1 = p0 + 1;

            // packed masks for the two pixels of this pair
            u64 mA[NST], mB[NST];
            mA[0] = msel(za[p0] >= 0.0f);   mB[0] = msel(za[p1] >= 0.0f);
            mA[1] = msel(ba0[p0] < zp[p0]); mB[1] = msel(ba0[p1] < zp[p1]);
            mA[2] = msel(ba1[p0] < zp[p0]); mB[2] = msel(ba1[p1] < zp[p1]);
            mA[3] = msel(ba2[p0] < zp[p0]); mB[3] = msel(ba2[p1] < zp[p1]);
            mA[4] = msel(ba3[p0] < zp[p0]); mB[4] = msel(ba3[p1] < zp[p1]);

            // broadcast x values for the two pixels
            u64 xb0 = pack2(xa0[p0], xa0[p0]);
            u64 xb1 = pack2(xa1[p0], xa1[p0]);
            u64 xb2 = pack2(xa2[p0], xa2[p0]);
            u64 yb0 = pack2(xa0[p1], xa0[p1]);
            u64 yb1 = pack2(xa1[p1], xa1[p1]);
            u64 yb2 = pack2(xa2[p1], xa2[p1]);

#pragma unroll
            for (int q = 0; q < NQ; q++) {
                ulonglong2 w0 = wpg[(0 * NQ + q) * (HWD / 2) + jp];
                ulonglong2 w1 = wpg[(1 * NQ + q) * (HWD / 2) + jp];
                ulonglong2 w2 = wpg[(2 * NQ + q) * (HWD / 2) + jp];

                u64 v0 = fma2(xb2, w2.x, fma2(xb1, w1.x, mul2(xb0, w0.x)));
                u64 v1 = fma2(yb2, w2.y, fma2(yb1, w1.y, mul2(yb0, w0.y)));

#pragma unroll
                for (int kk = 0; kk < NST; kk++) {
                    acc[kk][q] = fma2(mA[kk], v0, acc[kk][q]);
                    acc[kk][q] = fma2(mB[kk], v1, acc[kk][q]);
                }
            }
        }
    }

    // warp butterfly reduce (each warp = one batch), packed adds
#pragma unroll
    for (int kk = 0; kk < NST; kk++)
#pragma unroll
        for (int q = 0; q < NQ; q++) {
            u64 v = acc[kk][q];
#pragma unroll
            for (int off = 16; off > 0; off >>= 1)
                v = add2(v, __shfl_xor_sync(0xffffffffu, v, off));
            acc[kk][q] = v;
        }

    if (lane == 0) {
#pragma unroll
        for (int kk = 0; kk < NST; kk++)
#pragma unroll
            for (int q = 0; q < NQ; q++) {
                float flo, fhi;
                unpack2(acc[kk][q], flo, fhi);
                float* dst = &g_partial[((s * NST + kk) * BB + b) * NCL];
                dst[2 * q]     = flo;
                dst[2 * q + 1] = fhi;
            }
    }
}

// ---------------------------------------------------------------------------
// K2: sum slot partials, log-softmax -> pz, MH chain, select, write output.
// One thread per batch.
// ---------------------------------------------------------------------------
__global__ void final_kernel(const int* __restrict__ y,
                             const float* __restrict__ u,
                             const float* __restrict__ bias,
                             float* __restrict__ out)
{
    int b = blockIdx.x * blockDim.x + threadIdx.x;
    if (b >= BB) return;

    float logits[NST][NCL];
#pragma unroll
    for (int kk = 0; kk < NST; kk++)
#pragma unroll
        for (int n = 0; n < NCL; n++) {
            float sacc = 0.0f;
#pragma unroll
            for (int sc = 0; sc < SLOTS; sc++)
                sacc += g_partial[((sc * NST + kk) * BB + b) * NCL + n];
            logits[kk][n] = sacc + bias[n];
        }

    int yb = y[b];
    float pz[NST];
#pragma unroll
    for (int kk = 0; kk < NST; kk++) {
        float mx = logits[kk][0];
#pragma unroll
        for (int n = 1; n < NCL; n++) mx = fmaxf(mx, logits[kk][n]);
        float se = 0.0f;
#pragma unroll
        for (int n = 0; n < NCL; n++) se += expf(logits[kk][n] - mx);
        float lse = mx + logf(se);
        float ly = logits[kk][0];
#pragma unroll
        for (int n = 0; n < NCL; n++) if (n == yb) ly = logits[kk][n];
        pz[kk] = ly - lse;
    }

    // MH chain: accept when log(u) <= pz_cand - lp
    int sel = 0;
    float lp = pz[0];
#pragma unroll
    for (int k = 1; k < NST; k++) {
        float lu = logf(u[(k - 1) * BB + b]);
        if (lu <= pz[k] - lp) { sel = k; lp = pz[k]; }
    }

#pragma unroll
    for (int n = 0; n < NCL; n++) {
        float v = logits[0][n];
#pragma unroll
        for (int kk = 1; kk < NST; kk++) if (kk == sel) v = logits[kk][n];
        out[b * NCL + n] = v;
    }
}

// ---------------------------------------------------------------------------
extern "C" void kernel_launch(void* const* d_in, const int* in_sizes, int n_in,
                              void* d_out, int out_size)
{
    const float* zl   = (const float*)d_in[0];   // [256,1,128,128]
    const float* x    = (const float*)d_in[1];   // [256,3,128,128]
    const int*   y    = (const int*)  d_in[2];   // [256]
    const float* bern = (const float*)d_in[3];   // [4,256,1,128,128]
    const float* u    = (const float*)d_in[4];   // [4,256]
    const float* W    = (const float*)d_in[5];   // [49152,10]
    const float* bias = (const float*)d_in[6];   // [10]
    float* out = (float*)d_out;                  // [256,10]

    prep_kernel<<<(CC * HWD + 255) / 256, 256>>>(W);

    dim3 grid(SLOTS, BB / BG);
    main_kernel<<<grid, BG * 32>>>(zl, x, bern);

    final_kernel<<<1, BB>>>(y, u, bias, out);
}

// round 4
// speedup vs baseline: 1.7679x; 1.4830x over previous
#include <cuda_runtime.h>
#include <math.h>

// Problem constants (fixed by the reference setup)
#define BB   256      // batch
#define CC   3        // channels
#define HWD  16384    // H*W = 128*128
#define NST  5        // states evaluated: s0 + 4 candidates
#define NCL  10       // classes
#define NQ   5        // class pairs (NCL/2)
#define PAIRS (HWD / 2)   // 8192 pixel pairs per plane

// Tiling
#define BG     8              // batches per block (8 warps, 256 threads)
#define SLOTS  9              // pixel slots: 32*9=288 blocks ~ one 2/SM wave

typedef unsigned long long u64;

// Scratch (static device arrays: allocation-free)
__device__ ulonglong2 g_Wp[CC * NQ * PAIRS];    // [c][q][pair]{px0:(c2q,c2q+1), px1:(c2q,c2q+1)}
__device__ float g_partial[SLOTS * NST * BB * NCL];

// ---------------------------------------------------------------------------
// f32x2 packed-math helpers (sm_100+)
// ---------------------------------------------------------------------------
__device__ __forceinline__ u64 pack2(float lo, float hi) {
    u64 r; asm("mov.b64 %0, {%1, %2};" : "=l"(r) : "f"(lo), "f"(hi)); return r;
}
__device__ __forceinline__ u64 fma2(u64 a, u64 b, u64 c) {
    u64 d; asm("fma.rn.f32x2 %0, %1, %2, %3;" : "=l"(d) : "l"(a), "l"(b), "l"(c)); return d;
}
__device__ __forceinline__ u64 mul2(u64 a, u64 b) {
    u64 d; asm("mul.rn.f32x2 %0, %1, %2;" : "=l"(d) : "l"(a), "l"(b)); return d;
}
__device__ __forceinline__ u64 add2(u64 a, u64 b) {
    u64 d; asm("add.rn.f32x2 %0, %1, %2;" : "=l"(d) : "l"(a), "l"(b)); return d;
}
__device__ __forceinline__ void unpack2(u64 v, float& lo, float& hi) {
    asm("mov.b64 {%0, %1}, %2;" : "=f"(lo), "=f"(hi) : "l"(v));
}
__device__ __forceinline__ u64 msel(bool c) {
    return c ? 0x3f8000003f800000ULL : 0ULL;
}

// ---------------------------------------------------------------------------
// K0: repack W [CC*HWD, NCL] -> g_Wp [c][q][pixel] class-pair stream
// ---------------------------------------------------------------------------
__global__ void prep_kernel(const float* __restrict__ W)
{
    int r = blockIdx.x * blockDim.x + threadIdx.x;   // r in [0, CC*HWD)
    if (r < CC * HWD) {
        int c = r / HWD;
        int p = r - c * HWD;
        const float2* Wr = reinterpret_cast<const float2*>(W + (size_t)r * NCL); // 8B aligned (40B rows)
        float2* wp2 = reinterpret_cast<float2*>(g_Wp);
#pragma unroll
        for (int q = 0; q < NQ; q++)
            wp2[(c * NQ + q) * HWD + p] = Wr[q];
    }
}

// ---------------------------------------------------------------------------
// K1: fused mask generation + 5-state masked classifier partial sums.
// Grid: (SLOTS, BB/BG). Block: 8 warps; warp w = batch blockIdx.y*8 + w.
// Each lane processes one pixel-pair per iteration. Inputs streamed with
// evict-first (__ldcs) so the per-block W slot (~228KB) stays L1-resident.
// ---------------------------------------------------------------------------
__global__ __launch_bounds__(BG * 32, 2)
void main_kernel(const float* __restrict__ zl,
                 const float* __restrict__ x,
                 const float* __restrict__ bern)
{
    const int warp = threadIdx.x >> 5;
    const int lane = threadIdx.x & 31;
    const int b    = blockIdx.y * BG + warp;
    const int s    = blockIdx.x;

    const int lo = (s * PAIRS) / SLOTS;
    const int hi = ((s + 1) * PAIRS) / SLOTS;

    const float2* z2  = reinterpret_cast<const float2*>(zl) + b * PAIRS;
    const float2* x20 = reinterpret_cast<const float2*>(x) + (b * CC + 0) * PAIRS;
    const float2* x21 = reinterpret_cast<const float2*>(x) + (b * CC + 1) * PAIRS;
    const float2* x22 = reinterpret_cast<const float2*>(x) + (b * CC + 2) * PAIRS;
    const float2* bn0 = reinterpret_cast<const float2*>(bern) + (0 * BB + b) * PAIRS;
    const float2* bn1 = reinterpret_cast<const float2*>(bern) + (1 * BB + b) * PAIRS;
    const float2* bn2 = reinterpret_cast<const float2*>(bern) + (2 * BB + b) * PAIRS;
    const float2* bn3 = reinterpret_cast<const float2*>(bern) + (3 * BB + b) * PAIRS;
    const ulonglong2* wp = g_Wp;

    u64 acc[NST][NQ];
#pragma unroll
    for (int kk = 0; kk < NST; kk++)
#pragma unroll
        for (int q = 0; q < NQ; q++) acc[kk][q] = 0ULL;

    for (int t = lo + lane; t < hi; t += 32) {
        // streaming input loads (evict-first: keep L1 for W)
        float2 z  = __ldcs(z2 + t);
        float2 a0 = __ldcs(x20 + t);
        float2 a1 = __ldcs(x21 + t);
        float2 a2 = __ldcs(x22 + t);
        float2 c0 = __ldcs(bn0 + t);
        float2 c1 = __ldcs(bn1 + t);
        float2 c2 = __ldcs(bn2 + t);
        float2 c3 = __ldcs(bn3 + t);

        float zp0 = 1.0f / (1.0f + __expf(-z.x));
        float zp1 = 1.0f / (1.0f + __expf(-z.y));

        u64 mA[NST], mB[NST];
        mA[0] = msel(z.x >= 0.0f);  mB[0] = msel(z.y >= 0.0f);
        mA[1] = msel(c0.x < zp0);   mB[1] = msel(c0.y < zp1);
        mA[2] = msel(c1.x < zp0);   mB[2] = msel(c1.y < zp1);
        mA[3] = msel(c2.x < zp0);   mB[3] = msel(c2.y < zp1);
        mA[4] = msel(c3.x < zp0);   mB[4] = msel(c3.y < zp1);

        u64 xb0 = pack2(a0.x, a0.x);
        u64 xb1 = pack2(a1.x, a1.x);
        u64 xb2 = pack2(a2.x, a2.x);
        u64 yb0 = pack2(a0.y, a0.y);
        u64 yb1 = pack2(a1.y, a1.y);
        u64 yb2 = pack2(a2.y, a2.y);

#pragma unroll
        for (int q = 0; q < NQ; q++) {
            ulonglong2 w0 = __ldg(wp + (0 * NQ + q) * PAIRS + t);
            ulonglong2 w1 = __ldg(wp + (1 * NQ + q) * PAIRS + t);
            ulonglong2 w2 = __ldg(wp + (2 * NQ + q) * PAIRS + t);

            u64 v0 = fma2(xb2, w2.x, fma2(xb1, w1.x, mul2(xb0, w0.x)));
            u64 v1 = fma2(yb2, w2.y, fma2(yb1, w1.y, mul2(yb0, w0.y)));

#pragma unroll
            for (int kk = 0; kk < NST; kk++) {
                acc[kk][q] = fma2(mA[kk], v0, acc[kk][q]);
                acc[kk][q] = fma2(mB[kk], v1, acc[kk][q]);
            }
        }
    }

    // warp butterfly reduce (each warp = one batch), packed adds
#pragma unroll
    for (int kk = 0; kk < NST; kk++)
#pragma unroll
        for (int q = 0; q < NQ; q++) {
            u64 v = acc[kk][q];
#pragma unroll
            for (int off = 16; off > 0; off >>= 1)
                v = add2(v, __shfl_xor_sync(0xffffffffu, v, off));
            acc[kk][q] = v;
        }

    if (lane == 0) {
#pragma unroll
        for (int kk = 0; kk < NST; kk++)
#pragma unroll
            for (int q = 0; q < NQ; q++) {
                float flo, fhi;
                unpack2(acc[kk][q], flo, fhi);
                float* dst = &g_partial[((s * NST + kk) * BB + b) * NCL];
                dst[2 * q]     = flo;
                dst[2 * q + 1] = fhi;
            }
    }
}

// ---------------------------------------------------------------------------
// K2: sum slot partials, log-softmax -> pz, MH chain, select, write output.
// One thread per batch.
// ---------------------------------------------------------------------------
__global__ void final_kernel(const int* __restrict__ y,
                             const float* __restrict__ u,
                             const float* __restrict__ bias,
                             float* __restrict__ out)
{
    int b = blockIdx.x * blockDim.x + threadIdx.x;
    if (b >= BB) return;

    float logits[NST][NCL];
#pragma unroll
    for (int kk = 0; kk < NST; kk++)
#pragma unroll
        for (int n = 0; n < NCL; n++) {
            float sacc = 0.0f;
#pragma unroll
            for (int sc = 0; sc < SLOTS; sc++)
                sacc += g_partial[((sc * NST + kk) * BB + b) * NCL + n];
            logits[kk][n] = sacc + bias[n];
        }

    int yb = y[b];
    float pz[NST];
#pragma unroll
    for (int kk = 0; kk < NST; kk++) {
        float mx = logits[kk][0];
#pragma unroll
        for (int n = 1; n < NCL; n++) mx = fmaxf(mx, logits[kk][n]);
        float se = 0.0f;
#pragma unroll
        for (int n = 0; n < NCL; n++) se += expf(logits[kk][n] - mx);
        float lse = mx + logf(se);
        float ly = logits[kk][0];
#pragma unroll
        for (int n = 0; n < NCL; n++) if (n == yb) ly = logits[kk][n];
        pz[kk] = ly - lse;
    }

    // MH chain: accept when log(u) <= pz_cand - lp
    int sel = 0;
    float lp = pz[0];
#pragma unroll
    for (int k = 1; k < NST; k++) {
        float lu = logf(u[(k - 1) * BB + b]);
        if (lu <= pz[k] - lp) { sel = k; lp = pz[k]; }
    }

#pragma unroll
    for (int n = 0; n < NCL; n++) {
        float v = logits[0][n];
#pragma unroll
        for (int kk = 1; kk < NST; kk++) if (kk == sel) v = logits[kk][n];
        out[b * NCL + n] = v;
    }
}

// ---------------------------------------------------------------------------
extern "C" void kernel_launch(void* const* d_in, const int* in_sizes, int n_in,
                              void* d_out, int out_size)
{
    const float* zl   = (const float*)d_in[0];   // [256,1,128,128]
    const float* x    = (const float*)d_in[1];   // [256,3,128,128]
    const int*   y    = (const int*)  d_in[2];   // [256]
    const float* bern = (const float*)d_in[3];   // [4,256,1,128,128]
    const float* u    = (const float*)d_in[4];   // [4,256]
    const float* W    = (const float*)d_in[5];   // [49152,10]
    const float* bias = (const float*)d_in[6];   // [10]
    float* out = (float*)d_out;                  // [256,10]

    prep_kernel<<<(CC * HWD + 255) / 256, 256>>>(W);

    dim3 grid(SLOTS, BB / BG);
    main_kernel<<<grid, BG * 32>>>(zl, x, bern);

    final_kernel<<<1, BB>>>(y, u, bias, out);
}